// round 4
// baseline (speedup 1.0000x reference)
#include <cuda_runtime.h>

#define NQ    10
#define DIM   1024
#define NL    4
#define WARPS 4
#define TPB   (WARPS * 32)

typedef unsigned long long u64;

__device__ u64 g_gmat[NL * NQ][8];        // packed gate coefficient variants
__device__ unsigned g_T2p[2][DIM / 2];    // packed (lo,hi) gather tables

__device__ __forceinline__ u64 pack2(float x, float y) {
    u64 r; asm("mov.b64 %0, {%1,%2};" : "=l"(r) : "f"(x), "f"(y)); return r;
}
__device__ __forceinline__ void unpk(u64 v, float& x, float& y) {
    asm("mov.b64 {%0,%1}, %2;" : "=f"(x), "=f"(y) : "l"(v));
}
__device__ __forceinline__ u64 swp(u64 v) {
    u64 r;
    asm("{\n\t.reg .b32 lo, hi;\n\tmov.b64 {lo,hi}, %1;\n\tmov.b64 %0, {hi,lo};\n\t}"
        : "=l"(r) : "l"(v));
    return r;
}
__device__ __forceinline__ u64 ffma2(u64 a, u64 b, u64 c) {
    u64 d; asm("fma.rn.f32x2 %0, %1, %2, %3;" : "=l"(d) : "l"(a), "l"(b), "l"(c)); return d;
}
__device__ __forceinline__ u64 fmul2(u64 a, u64 b) {
    u64 d; asm("mul.rn.f32x2 %0, %1, %2;" : "=l"(d) : "l"(a), "l"(b)); return d;
}
__device__ __forceinline__ u64 fadd2(u64 a, u64 b) {
    u64 d; asm("add.rn.f32x2 %0, %1, %2;" : "=l"(d) : "l"(a), "l"(b)); return d;
}
__device__ __forceinline__ float2 cmulf(float2 a, float2 b) {
    return make_float2(a.x * b.x - a.y * b.y, a.x * b.y + a.y * b.x);
}

// ---- precompute kernel: gate coefficient packs + gather tables ----
__device__ __forceinline__ unsigned permphys(int type, unsigned idx) {
    int off = type ? (NQ / 2) : 1;
    unsigned y = idx;
    #pragma unroll
    for (int i = NQ - 1; i >= 0; --i) {
        int bc = NQ - 1 - i;
        int bt = NQ - 1 - ((i + off) % NQ);
        y ^= ((y >> bc) & 1u) << bt;
    }
    return (y & ~31u) | ((y ^ (y >> 5)) & 31u);
}

__global__ void precompute_kernel(const float* __restrict__ w) {
    int t = threadIdx.x;
    if (t < NL * NQ) {
        int q = t % NQ;
        float w0 = w[t * 3 + 0], w1 = w[t * 3 + 1], w2 = w[t * 3 + 2];
        float sb, cb; sincosf(0.5f * w1, &sb, &cb);
        float sp, cp; sincosf(0.5f * (w0 + w2), &sp, &cp);
        float sd, cd; sincosf(0.5f * (w0 - w2), &sd, &cd);
        // U = [[a, -conj(b)],[b, conj(a)]],  a=U00, b=U10
        float ar = cb * cp, ai = -cb * sp;
        float br = sb * cd, bi = -sb * sd;
        u64* g = g_gmat[t];
        if (q == 0 || q == 5) {       // bit-4 form (mixed-sign packs)
            g[0] = pack2(ar, ar);   g[1] = pack2(-br, br);
            g[2] = pack2(-ai, ai);  g[3] = pack2(-bi, -bi);
            g[4] = pack2(ai, -ai);  g[5] = pack2(bi, bi);
            g[6] = 0; g[7] = 0;
        } else {                      // cheap form (uniform packs + negatives)
            g[0] = pack2(ar, ar);   g[1] = pack2(ai, ai);  g[2] = pack2(-ai, -ai);
            g[3] = pack2(br, br);   g[4] = pack2(-br, -br);
            g[5] = pack2(bi, bi);   g[6] = pack2(-bi, -bi); g[7] = 0;
        }
    }
    for (int j2 = t; j2 < DIM; j2 += blockDim.x) {
        int type = j2 >> 9, wrd = j2 & 511;
        int l = wrd >> 4, m = wrd & 15;
        unsigned lo = permphys(type, (unsigned)(l * 32 + m));
        unsigned hi = permphys(type, (unsigned)(l * 32 + m + 16));
        g_T2p[type][wrd] = lo | (hi << 16);
    }
}

// ---- gate on k-bits 0..3 (mask M): pure FFMA2, no swaps ----
template<int M>
__device__ __forceinline__ void gate_cheap(u64* RE, u64* IM, const u64* __restrict__ G) {
    const u64 car = G[0], cai = G[1], nai = G[2];
    const u64 cbr = G[3], nbr = G[4], cbi = G[5], nbi = G[6];
    #pragma unroll
    for (int m = 0; m < 16; ++m) {
        if (!(m & M)) {
            const int m1 = m | M;
            u64 a0r = RE[m], a0i = IM[m], a1r = RE[m1], a1i = IM[m1];
            u64 n0r = ffma2(car, a0r, ffma2(nai, a0i, ffma2(nbr, a1r, fmul2(nbi, a1i))));
            u64 n0i = ffma2(car, a0i, ffma2(cai, a0r, ffma2(nbr, a1i, fmul2(cbi, a1r))));
            u64 n1r = ffma2(cbr, a0r, ffma2(nbi, a0i, ffma2(car, a1r, fmul2(cai, a1i))));
            u64 n1i = ffma2(cbr, a0i, ffma2(cbi, a0r, ffma2(car, a1i, fmul2(nai, a1r))));
            RE[m] = n0r; IM[m] = n0i; RE[m1] = n1r; IM[m1] = n1i;
        }
    }
}

// ---- gate on k-bit 4 (the packing bit): mixed-sign coeffs + half swaps ----
__device__ __forceinline__ void gate_b4(u64* RE, u64* IM, const u64* __restrict__ G) {
    const u64 D0 = G[0], D1 = G[1], D2 = G[2], D3 = G[3], D4 = G[4], D5 = G[5];
    #pragma unroll
    for (int m = 0; m < 16; ++m) {
        u64 vr = RE[m], vi = IM[m], sr = swp(vr), si = swp(vi);
        u64 nr = ffma2(D0, vr, ffma2(D1, sr, ffma2(D2, vi, fmul2(D3, si))));
        u64 ni = ffma2(D0, vi, ffma2(D1, si, ffma2(D4, vr, fmul2(D5, sr))));
        RE[m] = nr; IM[m] = ni;
    }
}

__global__ __launch_bounds__(TPB, 4) void qsim_kernel(
    const float* __restrict__ x,     // (B, 2*NQ)
    float* __restrict__ out)         // (B, NQ)
{
    __shared__ float sc_re[WARPS][DIM];        // 16 KB
    __shared__ float sc_im[WARPS][DIM];        // 16 KB
    __shared__ u64 gmat_s[NL * NQ][8];         // 2.5 KB
    __shared__ unsigned Tp_s[2][DIM / 2];      // 4 KB
    __shared__ float2 venc[WARPS][NQ][2];

    const int t    = threadIdx.x;
    const int lane = t & 31;
    const int wid  = t >> 5;
    const int s    = blockIdx.x * WARPS + wid;
    const float inv_sqrt2 = 0.70710678118654752440f;
    const float pi_f      = 3.14159265358979323846f;

    // copy precomputed tables into smem
    {
        const u64* src = &g_gmat[0][0];
        u64* dst = &gmat_s[0][0];
        for (int i = t; i < NL * NQ * 8; i += TPB) dst[i] = src[i];
        const unsigned* ts = &g_T2p[0][0];
        unsigned* td = &Tp_s[0][0];
        for (int i = t; i < DIM; i += TPB) td[i] = ts[i];
    }
    // per-sample encoding columns: v = RZ(phi)*RY(theta)*H |0>
    if (lane < NQ) {
        int q = lane;
        float th = 0.5f * pi_f * (x[s * 2 * NQ + q]      + 1.0f);
        float ph = 0.5f * pi_f * (x[s * 2 * NQ + NQ + q] + 1.0f);
        float st, ct; sincosf(0.5f * th, &st, &ct);
        float sh, ch; sincosf(0.5f * ph, &sh, &ch);
        float a = inv_sqrt2 * (ct - st);
        float b = inv_sqrt2 * (ct + st);
        venc[wid][q][0] = make_float2(a * ch, -a * sh);
        venc[wid][q][1] = make_float2(b * ch,  b * sh);
    }
    __syncthreads();

    // ---- build product state, SoA-packed: RE[m]=(re_k, re_{k+16}), k=m ----
    // layout A: amp j = lane*32 + k ; j bit (9-q) <-> qubit q
    u64 RE[16], IM[16];
    {
        float2 L = venc[wid][0][(lane >> 4) & 1];
        L = cmulf(L, venc[wid][1][(lane >> 3) & 1]);
        L = cmulf(L, venc[wid][2][(lane >> 2) & 1]);
        L = cmulf(L, venc[wid][3][(lane >> 1) & 1]);
        L = cmulf(L, venc[wid][4][lane & 1]);
        float2 L0 = cmulf(L, venc[wid][5][0]);
        float2 L1 = cmulf(L, venc[wid][5][1]);
        #pragma unroll
        for (int m = 0; m < 16; ++m) {
            float2 Rm = cmulf(cmulf(venc[wid][6][(m >> 3) & 1], venc[wid][7][(m >> 2) & 1]),
                              cmulf(venc[wid][8][(m >> 1) & 1], venc[wid][9][m & 1]));
            float2 c0 = cmulf(L0, Rm);
            float2 c1 = cmulf(L1, Rm);
            RE[m] = pack2(c0.x, c1.x);
            IM[m] = pack2(c0.y, c1.y);
        }
    }

    float* sre = sc_re[wid];
    float* sim = sc_im[wid];

    #pragma unroll 1
    for (int layer = 0; layer < NL; ++layer) {
        const u64 (*G)[8] = &gmat_s[layer * NQ];
        // layout A: k bits 4..0 <-> qubits 5..9
        gate_b4(RE, IM, G[5]);
        gate_cheap<8>(RE, IM, G[6]);
        gate_cheap<4>(RE, IM, G[7]);
        gate_cheap<2>(RE, IM, G[8]);
        gate_cheap<1>(RE, IM, G[9]);
        // transpose A -> B (conflict-free swizzled)
        #pragma unroll
        for (int m = 0; m < 16; ++m) {
            float lo, hi, li, hh;
            unpk(RE[m], lo, hi); unpk(IM[m], li, hh);
            sre[lane * 32 + (m ^ lane)]        = lo;
            sre[lane * 32 + ((m + 16) ^ lane)] = hi;
            sim[lane * 32 + (m ^ lane)]        = li;
            sim[lane * 32 + ((m + 16) ^ lane)] = hh;
        }
        __syncwarp();
        #pragma unroll
        for (int m = 0; m < 16; ++m) {
            float lo = sre[m * 32 + (lane ^ m)];
            float hi = sre[(m + 16) * 32 + (lane ^ (m + 16))];
            float li = sim[m * 32 + (lane ^ m)];
            float hh = sim[(m + 16) * 32 + (lane ^ (m + 16))];
            RE[m] = pack2(lo, hi);
            IM[m] = pack2(li, hh);
        }
        __syncwarp();
        // layout B: k bits 4..0 <-> qubits 0..4
        gate_b4(RE, IM, G[0]);
        gate_cheap<8>(RE, IM, G[1]);
        gate_cheap<4>(RE, IM, G[2]);
        gate_cheap<2>(RE, IM, G[3]);
        gate_cheap<1>(RE, IM, G[4]);
        // CNOT ring + transpose-back, composed into one swizzled gather
        #pragma unroll
        for (int m = 0; m < 16; ++m) {
            float lo, hi, li, hh;
            unpk(RE[m], lo, hi); unpk(IM[m], li, hh);
            sre[m * 32 + (lane ^ m)]               = lo;
            sre[(m + 16) * 32 + (lane ^ (m + 16))] = hi;
            sim[m * 32 + (lane ^ m)]               = li;
            sim[(m + 16) * 32 + (lane ^ (m + 16))] = hh;
        }
        __syncwarp();
        const unsigned* T = Tp_s[layer & 1];
        #pragma unroll
        for (int m = 0; m < 16; ++m) {
            unsigned tw = T[lane * 16 + m];
            unsigned i0 = tw & 0xffffu, i1 = tw >> 16;
            RE[m] = pack2(sre[i0], sre[i1]);
            IM[m] = pack2(sim[i0], sim[i1]);
        }
        __syncwarp();
    }

    // ---- <Z_q> readout (packed probabilities) ----
    u64 tot = 0, accP[4] = {0, 0, 0, 0}, accN[4] = {0, 0, 0, 0};
    #pragma unroll
    for (int m = 0; m < 16; ++m) {
        u64 pr = ffma2(RE[m], RE[m], fmul2(IM[m], IM[m]));
        tot = fadd2(tot, pr);
        #pragma unroll
        for (int b = 0; b < 4; ++b) {
            if ((m >> b) & 1) accN[b] = fadd2(accN[b], pr);
            else              accP[b] = fadd2(accP[b], pr);
        }
    }
    float zq[NQ];
    {
        float tl, thh; unpk(tot, tl, thh);
        float pr_tot = tl + thh;
        zq[5] = tl - thh;                     // qubit5 = packing bit
        #pragma unroll
        for (int b = 0; b < 4; ++b) {         // m bit b <-> qubit 9-b
            float pl, ph2, nl, nh;
            unpk(accP[b], pl, ph2); unpk(accN[b], nl, nh);
            zq[9 - b] = (pl + ph2) - (nl + nh);
        }
        zq[0] = ((lane >> 4) & 1) ? -pr_tot : pr_tot;
        zq[1] = ((lane >> 3) & 1) ? -pr_tot : pr_tot;
        zq[2] = ((lane >> 2) & 1) ? -pr_tot : pr_tot;
        zq[3] = ((lane >> 1) & 1) ? -pr_tot : pr_tot;
        zq[4] = (lane & 1)        ? -pr_tot : pr_tot;
    }
    #pragma unroll
    for (int q = 0; q < NQ; ++q) {
        #pragma unroll
        for (int o = 16; o > 0; o >>= 1)
            zq[q] += __shfl_xor_sync(0xffffffffu, zq[q], o);
    }
    if (lane == 0) {
        #pragma unroll
        for (int q = 0; q < NQ; ++q)
            out[s * NQ + q] = zq[q];
    }
}

extern "C" void kernel_launch(void* const* d_in, const int* in_sizes, int n_in,
                              void* d_out, int out_size) {
    const float* x = (const float*)d_in[0];
    const float* w = (const float*)d_in[1];
    float* out = (float*)d_out;
    int B = in_sizes[0] / (2 * NQ);   // 4096 flattened samples
    precompute_kernel<<<1, 128>>>(w);
    qsim_kernel<<<B / WARPS, TPB>>>(x, out);
}

// round 5
// speedup vs baseline: 1.0425x; 1.0425x over previous
#include <cuda_runtime.h>

#define NQ  10
#define DIM 1024
#define NL  4
#define TPB 64

typedef unsigned long long u64;

__device__ u64 g_gmat[NL * NQ][8];          // packed gate coefficients
__device__ unsigned short g_T[2][DIM];      // swizzled gather tables (+b flag bit15)

__device__ __forceinline__ u64 pack2(float x, float y) {
    u64 r; asm("mov.b64 %0, {%1,%2};" : "=l"(r) : "f"(x), "f"(y)); return r;
}
__device__ __forceinline__ void unpk(u64 v, float& x, float& y) {
    asm("mov.b64 {%0,%1}, %2;" : "=f"(x), "=f"(y) : "l"(v));
}
__device__ __forceinline__ u64 swp(u64 v) {
    u64 r;
    asm("{\n\t.reg .b32 lo, hi;\n\tmov.b64 {lo,hi}, %1;\n\tmov.b64 %0, {hi,lo};\n\t}"
        : "=l"(r) : "l"(v));
    return r;
}
__device__ __forceinline__ u64 ffma2(u64 a, u64 b, u64 c) {
    u64 d; asm("fma.rn.f32x2 %0, %1, %2, %3;" : "=l"(d) : "l"(a), "l"(b), "l"(c)); return d;
}
__device__ __forceinline__ u64 fmul2(u64 a, u64 b) {
    u64 d; asm("mul.rn.f32x2 %0, %1, %2;" : "=l"(d) : "l"(a), "l"(b)); return d;
}
__device__ __forceinline__ u64 fadd2(u64 a, u64 b) {
    u64 d; asm("add.rn.f32x2 %0, %1, %2;" : "=l"(d) : "l"(a), "l"(b)); return d;
}
__device__ __forceinline__ float2 cmulf(float2 a, float2 b) {
    return make_float2(a.x * b.x - a.y * b.y, a.x * b.y + a.y * b.x);
}

__device__ __forceinline__ unsigned finv(int type, unsigned idx) {
    int off = type ? (NQ / 2) : 1;
    unsigned y = idx;
    #pragma unroll
    for (int i = NQ - 1; i >= 0; --i) {
        int bc = NQ - 1 - i;
        int bt = NQ - 1 - ((i + off) % NQ);
        y ^= ((y >> bc) & 1u) << bt;
    }
    return y;
}

__global__ void precompute_kernel(const float* __restrict__ w) {
    int t = threadIdx.x;
    if (t < NL * NQ) {
        int q = t % NQ;
        float w0 = w[t * 3 + 0], w1 = w[t * 3 + 1], w2 = w[t * 3 + 2];
        float sb, cb; sincosf(0.5f * w1, &sb, &cb);
        float sp, cp; sincosf(0.5f * (w0 + w2), &sp, &cp);
        float sd, cd; sincosf(0.5f * (w0 - w2), &sd, &cd);
        // U = [[a, -conj(b)],[b, conj(a)]]; a=(ar,ai), b=(br,bi)
        float ar = cb * cp, ai = -cb * sp;
        float br = sb * cd, bi = -sb * sd;
        u64* g = g_gmat[t];
        if (q == 0) {
            // merged-gather layout: {c00,d00,c01,d01, c11,d11,c10,d10}
            g[0] = pack2(ar, ar);   g[1] = pack2(-ai, ai);
            g[2] = pack2(-br, -br); g[3] = pack2(-bi, bi);
            g[4] = pack2(ar, ar);   g[5] = pack2(ai, -ai);
            g[6] = pack2(br, br);   g[7] = pack2(-bi, bi);
        } else {
            // standard layout: {c00,d00,c01,d01,c10,d10,c11,d11}
            g[0] = pack2(ar, ar);   g[1] = pack2(-ai, ai);
            g[2] = pack2(-br, -br); g[3] = pack2(-bi, bi);
            g[4] = pack2(br, br);   g[5] = pack2(-bi, bi);
            g[6] = pack2(ar, ar);   g[7] = pack2(ai, -ai);
        }
    }
    for (int jj = t; jj < 2 * DIM; jj += blockDim.x) {
        int type = jj >> 10;
        unsigned j = jj & (DIM - 1);
        unsigned y = finv(type, j);
        unsigned phys = (y & ~31u) | ((y ^ (y >> 5)) & 31u);       // state swizzle
        unsigned short e = (unsigned short)(phys | ((y >> 9) << 15));
        unsigned iT = j ^ (((j >> 5) & 15u) << 1);                  // table swizzle (keeps bit0)
        g_T[type][iT] = e;
    }
}

// gate on k-bit mask M over 16 packed-complex amps
template<int M>
__device__ __forceinline__ void gate_reg(u64* r, const u64* __restrict__ C) {
    const u64 c00 = C[0], d00 = C[1], c01 = C[2], d01 = C[3];
    const u64 c10 = C[4], d10 = C[5], c11 = C[6], d11 = C[7];
    #pragma unroll
    for (int k = 0; k < 16; ++k) {
        if ((k & M) == 0) {
            const int k1 = k | M;
            u64 a0 = r[k], a1 = r[k1];
            u64 s0 = swp(a0), s1 = swp(a1);
            r[k]  = ffma2(c00, a0, ffma2(d00, s0, ffma2(c01, a1, fmul2(d01, s1))));
            r[k1] = ffma2(c10, a0, ffma2(d10, s0, ffma2(c11, a1, fmul2(d11, s1))));
        }
    }
}

// gate on lane-bit xor distance D
template<int D>
__device__ __forceinline__ void gate_shfl(u64* r, const u64* __restrict__ C, int lane) {
    const bool b = (lane & D) != 0;
    const u64 cA = b ? C[6] : C[0];
    const u64 dA = b ? C[7] : C[1];
    const u64 cB = b ? C[4] : C[2];
    const u64 dB = b ? C[5] : C[3];
    #pragma unroll
    for (int k = 0; k < 16; ++k) {
        u64 own = r[k];
        u64 par = __shfl_xor_sync(0xffffffffu, own, D);
        r[k] = ffma2(cA, own, ffma2(dA, swp(own), ffma2(cB, par, fmul2(dB, swp(par)))));
    }
}

__global__ __launch_bounds__(TPB, 12) void qsim_kernel(
    const float* __restrict__ x,     // (B, 2*NQ)
    float* __restrict__ out)         // (B, NQ)
{
    __shared__ u64 sc[DIM];                    // 8 KB state scratch (swizzled)
    __shared__ u64 gmat_s[NL * NQ][8];         // 2.5 KB
    __shared__ unsigned Tp_s[2][DIM / 2];      // 4 KB (u16 pairs)
    __shared__ float2 venc[NQ][2];
    __shared__ float red[2][NQ];

    const int t    = threadIdx.x;
    const int lane = t & 31;
    const int w    = t >> 5;                   // warp half = qubit-0 bit (j9)
    const int s    = blockIdx.x;
    const float inv_sqrt2 = 0.70710678118654752440f;
    const float pi_f      = 3.14159265358979323846f;

    // copy precomputed tables to smem
    {
        const u64* src = &g_gmat[0][0];
        u64* dst = &gmat_s[0][0];
        for (int i = t; i < NL * NQ * 8; i += TPB) dst[i] = src[i];
        const unsigned* ts = (const unsigned*)&g_T[0][0];
        unsigned* td = &Tp_s[0][0];
        for (int i = t; i < DIM; i += TPB) td[i] = ts[i];
    }
    if (t < NQ) {
        int q = t;
        float th = 0.5f * pi_f * (x[s * 2 * NQ + q]      + 1.0f);
        float ph = 0.5f * pi_f * (x[s * 2 * NQ + NQ + q] + 1.0f);
        float st, ct; sincosf(0.5f * th, &st, &ct);
        float sh, ch; sincosf(0.5f * ph, &sh, &ch);
        float a = inv_sqrt2 * (ct - st);
        float b = inv_sqrt2 * (ct + st);
        venc[q][0] = make_float2(a * ch, -a * sh);
        venc[q][1] = make_float2(b * ch,  b * sh);
    }
    __syncthreads();

    // ---- build product state: j = w*512 + lane*16 + k ; qubit q <-> j bit (9-q) ----
    u64 r[16];
    {
        float2 L = venc[0][w];
        L = cmulf(L, venc[1][(lane >> 4) & 1]);
        L = cmulf(L, venc[2][(lane >> 3) & 1]);
        L = cmulf(L, venc[3][(lane >> 2) & 1]);
        L = cmulf(L, venc[4][(lane >> 1) & 1]);
        L = cmulf(L, venc[5][lane & 1]);
        float2 RH[4], RL[4];
        #pragma unroll
        for (int h = 0; h < 4; ++h) RH[h] = cmulf(venc[6][(h >> 1) & 1], venc[7][h & 1]);
        #pragma unroll
        for (int l = 0; l < 4; ++l) RL[l] = cmulf(venc[8][(l >> 1) & 1], venc[9][l & 1]);
        #pragma unroll
        for (int k = 0; k < 16; ++k) {
            float2 a = cmulf(L, cmulf(RH[k >> 2], RL[k & 3]));
            r[k] = pack2(a.x, a.y);
        }
    }

    const int basej = w * 512 + lane * 16;
    const int X2    = ((lane & 1) << 4) ^ (w << 4) ^ (lane >> 1);  // phys low5 = k ^ X2
    const int C0    = basej & ~31;
    const int iTX   = (lane >> 1) << 1;                            // table swizzle xor

    #pragma unroll 1
    for (int layer = 0; layer < NL; ++layer) {
        const u64 (*G)[8] = &gmat_s[layer * NQ];
        // qubits 6..9 on k bits
        gate_reg<8>(r, G[6]);
        gate_reg<4>(r, G[7]);
        gate_reg<2>(r, G[8]);
        gate_reg<1>(r, G[9]);
        // qubits 1..5 on lane bits
        gate_shfl<16>(r, G[1], lane);
        gate_shfl<8>(r, G[2], lane);
        gate_shfl<4>(r, G[3], lane);
        gate_shfl<2>(r, G[4], lane);
        gate_shfl<1>(r, G[5], lane);
        // store state (swizzled, conflict-free)
        #pragma unroll
        for (int k = 0; k < 16; ++k)
            sc[C0 | (k ^ X2)] = r[k];
        __syncthreads();
        // gather = CNOT ring composed with qubit-0 gate
        const unsigned* T = Tp_s[layer & 1];
        const u64 q0_0 = G[0][0], q0_1 = G[0][1], q0_2 = G[0][2], q0_3 = G[0][3];
        const u64 q1_0 = G[0][4], q1_1 = G[0][5], q1_2 = G[0][6], q1_3 = G[0][7];
        #pragma unroll
        for (int kp = 0; kp < 8; ++kp) {
            const int k = kp * 2;
            unsigned iT = (unsigned)((basej | k) ^ iTX);
            unsigned tw = T[iT >> 1];
            #pragma unroll
            for (int h = 0; h < 2; ++h) {
                unsigned e = (h == 0) ? (tw & 0xffffu) : (tw >> 16);
                unsigned idx = e & 1023u;
                bool bb = (e >> 15) != 0;
                u64 a = sc[idx];
                u64 p = sc[idx ^ 0x210u];
                u64 cA = bb ? q1_0 : q0_0;
                u64 dA = bb ? q1_1 : q0_1;
                u64 cB = bb ? q1_2 : q0_2;
                u64 dB = bb ? q1_3 : q0_3;
                r[k + h] = ffma2(cA, a, ffma2(dA, swp(a), ffma2(cB, p, fmul2(dB, swp(p)))));
            }
        }
        __syncthreads();
    }

    // ---- <Z_q> readout ----
    u64 tot = 0, accP[4] = {0,0,0,0}, accN[4] = {0,0,0,0};
    #pragma unroll
    for (int k = 0; k < 16; ++k) {
        u64 sq = fmul2(r[k], r[k]);          // (re^2, im^2)
        tot = fadd2(tot, sq);
        #pragma unroll
        for (int b = 0; b < 4; ++b) {
            if ((k >> b) & 1) accN[b] = fadd2(accN[b], sq);
            else              accP[b] = fadd2(accP[b], sq);
        }
    }
    float zq[NQ];
    {
        float tl, th; unpk(tot, tl, th);
        float pr_tot = tl + th;
        zq[0] = w ? -pr_tot : pr_tot;
        zq[1] = (lane & 16) ? -pr_tot : pr_tot;
        zq[2] = (lane & 8)  ? -pr_tot : pr_tot;
        zq[3] = (lane & 4)  ? -pr_tot : pr_tot;
        zq[4] = (lane & 2)  ? -pr_tot : pr_tot;
        zq[5] = (lane & 1)  ? -pr_tot : pr_tot;
        #pragma unroll
        for (int b = 0; b < 4; ++b) {        // k bit b <-> qubit 9-b
            float pl, ph, nl, nh;
            unpk(accP[b], pl, ph); unpk(accN[b], nl, nh);
            zq[9 - b] = (pl + ph) - (nl + nh);
        }
    }
    #pragma unroll
    for (int q = 0; q < NQ; ++q) {
        #pragma unroll
        for (int o = 16; o > 0; o >>= 1)
            zq[q] += __shfl_xor_sync(0xffffffffu, zq[q], o);
    }
    if (lane == 0) {
        #pragma unroll
        for (int q = 0; q < NQ; ++q) red[w][q] = zq[q];
    }
    __syncthreads();
    if (t < NQ)
        out[s * NQ + t] = red[0][t] + red[1][t];
}

extern "C" void kernel_launch(void* const* d_in, const int* in_sizes, int n_in,
                              void* d_out, int out_size) {
    const float* x = (const float*)d_in[0];
    const float* w = (const float*)d_in[1];
    float* out = (float*)d_out;
    int B = in_sizes[0] / (2 * NQ);   // 4096 flattened samples
    precompute_kernel<<<1, 128>>>(w);
    qsim_kernel<<<B, TPB>>>(x, out);
}